// round 1
// baseline (speedup 1.0000x reference)
#include <cuda_runtime.h>
#include <cstdint>
#include <cmath>

#define NCCOM 100000
#define NTOP  5000
#define NCLM  20000
#define DC 256
#define HD 128
#define ESIM 600000
#define EAB  300000
#define ETG  300000
#define ETOT (ESIM+EAB+ETG)

// ---------------- device scratch (no runtime allocation allowed) ----------------
static __device__ float g_y1[(size_t)NCCOM * 256];      // [Wl | Wr_sum] products (both layers, reused)
static __device__ float g_h1[(size_t)NCCOM * HD];       // h1, then h
static __device__ float g_agg[3][(size_t)NCCOM * HD];   // per-edge-type segment sums
static __device__ float g_yt[(size_t)NTOP * 256];       // topic @ [c1a_Wl | c2a_Wl]
static __device__ float g_yc[(size_t)NCLM * 256];       // claim @ [c1t_Wl | c2t_Wl]
static __device__ float g_cnt[3][NCCOM];                // in-degree per edge type
static __device__ int   g_src[ETOT];
static __device__ int   g_dst[ETOT];
static __device__ float g_W1[256 * 256];                // [c1s_Wl | c1s_Wr+c1a_Wr+c1t_Wr]
static __device__ float g_W2[128 * 256];                // [c2s_Wl | c2s_Wr+c2a_Wr+c2t_Wr]
static __device__ float g_Wtc[128 * 256];               // [c1a_Wl | c2a_Wl]
static __device__ float g_Wcc[128 * 256];               // [c1t_Wl | c2t_Wl]
static __device__ float g_b1[128];
static __device__ float g_b2[128];
static __device__ int   g_is64;

// ---------------- edge index dtype detection + normalization ----------------
__global__ void detect_kernel(const int* __restrict__ raw) {
    // int64 little-endian: high words (odd int32 positions) of positive indices are 0.
    // int32: odd positions are random indices in [0,100000); prob all-zero ~ 0.
    int allz = 1;
    for (int i = 0; i < 32; i++)
        if (raw[2 * i + 1] != 0) { allz = 0; break; }
    g_is64 = allz;
}

__global__ void convert_edges(const int* __restrict__ raw, int* __restrict__ src,
                              int* __restrict__ dst, int E) {
    int e = blockIdx.x * blockDim.x + threadIdx.x;
    if (e >= E) return;
    if (g_is64) {
        src[e] = raw[2 * (size_t)e];
        dst[e] = raw[2 * ((size_t)E + e)];
    } else {
        src[e] = raw[e];
        dst[e] = raw[(size_t)E + e];
    }
}

// ---------------- combined weight construction ----------------
__global__ void build_weights(
    const float* __restrict__ c1sWl, const float* __restrict__ c1sWr,
    const float* __restrict__ c1aWr, const float* __restrict__ c1tWr,
    const float* __restrict__ c2sWl, const float* __restrict__ c2sWr,
    const float* __restrict__ c2aWr, const float* __restrict__ c2tWr,
    const float* __restrict__ c1aWl, const float* __restrict__ c2aWl,
    const float* __restrict__ c1tWl, const float* __restrict__ c2tWl,
    const float* __restrict__ b1s, const float* __restrict__ b1a, const float* __restrict__ b1t,
    const float* __restrict__ b2s, const float* __restrict__ b2a, const float* __restrict__ b2t)
{
    int i = blockIdx.x * blockDim.x + threadIdx.x;
    if (i < 65536) {                      // W1: [256, 256]
        int k = i >> 8, j = i & 255;
        g_W1[i] = (j < 128) ? c1sWl[k * 128 + j]
                            : (c1sWr[k * 128 + j - 128] + c1aWr[k * 128 + j - 128] + c1tWr[k * 128 + j - 128]);
    } else if (i < 98304) {               // W2: [128, 256]
        int t = i - 65536; int k = t >> 8, j = t & 255;
        g_W2[t] = (j < 128) ? c2sWl[k * 128 + j]
                            : (c2sWr[k * 128 + j - 128] + c2aWr[k * 128 + j - 128] + c2tWr[k * 128 + j - 128]);
    } else if (i < 131072) {              // Wtc: [128, 256]
        int t = i - 98304; int k = t >> 8, j = t & 255;
        g_Wtc[t] = (j < 128) ? c1aWl[k * 128 + j] : c2aWl[k * 128 + j - 128];
    } else if (i < 163840) {              // Wcc: [128, 256]
        int t = i - 131072; int k = t >> 8, j = t & 255;
        g_Wcc[t] = (j < 128) ? c1tWl[k * 128 + j] : c2tWl[k * 128 + j - 128];
    } else if (i < 163840 + 256) {
        int t = i - 163840;
        if (t < 128) g_b1[t] = b1s[t] + b1a[t] + b1t[t];
        else { int u = t - 128; g_b2[u] = b2s[u] + b2a[u] + b2t[u]; }
    }
}

// ---------------- zero ----------------
__global__ void zero_kernel(float* __restrict__ p, size_t n4) {
    size_t stride = (size_t)gridDim.x * blockDim.x;
    for (size_t i = blockIdx.x * (size_t)blockDim.x + threadIdx.x; i < n4; i += stride)
        ((float4*)p)[i] = make_float4(0.f, 0.f, 0.f, 0.f);
}

// ---------------- degree count ----------------
__global__ void count_kernel(const int* __restrict__ dst, float* __restrict__ cnt, int E) {
    int e = blockIdx.x * blockDim.x + threadIdx.x;
    if (e >= E) return;
    atomicAdd(&cnt[dst[e]], 1.0f);
}

// ---------------- SIMT fp32 GEMM: C[M,N] = A[M,K] @ B[K,N], row-major ----------------
template <int BM, int BN, int BK, int TM, int TN>
__global__ void __launch_bounds__((BM / TM) * (BN / TN))
gemm_f32(const float* __restrict__ A, const float* __restrict__ B, float* __restrict__ C,
         int M, int N, int K)
{
    constexpr int THREADS = (BM / TM) * (BN / TN);
    __shared__ float As[BK][BM + 4];
    __shared__ float Bs[BK][BN];
    const int tid = threadIdx.x;
    const int tx = tid % (BN / TN);
    const int ty = tid / (BN / TN);
    const int bm0 = blockIdx.x * BM;
    const int bn0 = blockIdx.y * BN;

    float acc[TM][TN];
#pragma unroll
    for (int i = 0; i < TM; i++)
#pragma unroll
        for (int j = 0; j < TN; j++) acc[i][j] = 0.f;

    for (int k0 = 0; k0 < K; k0 += BK) {
#pragma unroll
        for (int f = tid; f < BM * BK / 4; f += THREADS) {
            int row = f / (BK / 4);
            int k4 = f % (BK / 4);
            float4 v = make_float4(0.f, 0.f, 0.f, 0.f);
            if (bm0 + row < M)
                v = *(const float4*)(A + (size_t)(bm0 + row) * K + k0 + k4 * 4);
            As[k4 * 4 + 0][row] = v.x;
            As[k4 * 4 + 1][row] = v.y;
            As[k4 * 4 + 2][row] = v.z;
            As[k4 * 4 + 3][row] = v.w;
        }
#pragma unroll
        for (int f = tid; f < BK * BN / 4; f += THREADS) {
            int kr = f / (BN / 4);
            int c4 = f % (BN / 4);
            *(float4*)&Bs[kr][c4 * 4] = *(const float4*)(B + (size_t)(k0 + kr) * N + bn0 + c4 * 4);
        }
        __syncthreads();
#pragma unroll
        for (int kk = 0; kk < BK; kk++) {
            float ra[TM], rb[TN];
#pragma unroll
            for (int i = 0; i < TM; i += 4) *(float4*)&ra[i] = *(const float4*)&As[kk][ty * TM + i];
#pragma unroll
            for (int j = 0; j < TN; j += 4) *(float4*)&rb[j] = *(const float4*)&Bs[kk][tx * TN + j];
#pragma unroll
            for (int i = 0; i < TM; i++)
#pragma unroll
                for (int j = 0; j < TN; j++) acc[i][j] += ra[i] * rb[j];
        }
        __syncthreads();
    }
#pragma unroll
    for (int i = 0; i < TM; i++) {
        int r = bm0 + ty * TM + i;
        if (r >= M) break;
#pragma unroll
        for (int j = 0; j < TN; j += 4)
            *(float4*)(C + (size_t)r * N + bn0 + tx * TN + j) =
                make_float4(acc[i][j], acc[i][j + 1], acc[i][j + 2], acc[i][j + 3]);
    }
}

// ---------------- edge scatter: agg[dst] += y[src] (128 floats, v4 red) ----------------
__global__ void scatter_kernel(const float* __restrict__ y, int ldy,
                               const int* __restrict__ src, const int* __restrict__ dst,
                               float* __restrict__ agg, int E)
{
    int g = blockIdx.x * blockDim.x + threadIdx.x;
    int e = g >> 5;
    if (e >= E) return;
    int lane = g & 31;
    int s = __ldg(src + e);
    int d = __ldg(dst + e);
    float4 v = *(const float4*)(y + (size_t)s * ldy + lane * 4);
    float* p = agg + (size_t)d * HD + lane * 4;
    asm volatile("red.global.add.v4.f32 [%0], {%1,%2,%3,%4};"
                 :: "l"(p), "f"(v.x), "f"(v.y), "f"(v.z), "f"(v.w)
                 : "memory");
}

// ---------------- combine: out = relu(sum_t agg_t/max(cnt_t,1) + self + bias) ----------------
__global__ void combine_kernel(const float* __restrict__ agg0, const float* __restrict__ agg1,
                               const float* __restrict__ agg2,
                               const float* __restrict__ c0, const float* __restrict__ c1,
                               const float* __restrict__ c2,
                               const float* __restrict__ selfp, /* stride 256 */
                               const float* __restrict__ bias, float* __restrict__ out)
{
    int idx = blockIdx.x * blockDim.x + threadIdx.x;
    if (idx >= NCCOM * 32) return;
    int row = idx >> 5;
    int q = idx & 31;
    float i0 = 1.f / fmaxf(c0[row], 1.f);
    float i1 = 1.f / fmaxf(c1[row], 1.f);
    float i2 = 1.f / fmaxf(c2[row], 1.f);
    float4 a0 = *(const float4*)(agg0 + (size_t)row * HD + q * 4);
    float4 a1 = *(const float4*)(agg1 + (size_t)row * HD + q * 4);
    float4 a2 = *(const float4*)(agg2 + (size_t)row * HD + q * 4);
    float4 sv = *(const float4*)(selfp + (size_t)row * 256 + q * 4);
    float4 bv = *(const float4*)(bias + q * 4);
    float4 r;
    r.x = fmaxf(a0.x * i0 + a1.x * i1 + a2.x * i2 + sv.x + bv.x, 0.f);
    r.y = fmaxf(a0.y * i0 + a1.y * i1 + a2.y * i2 + sv.y + bv.y, 0.f);
    r.z = fmaxf(a0.z * i0 + a1.z * i1 + a2.z * i2 + sv.z + bv.z, 0.f);
    r.w = fmaxf(a0.w * i0 + a1.w * i1 + a2.w * i2 + sv.w + bv.w, 0.f);
    *(float4*)(out + (size_t)row * HD + q * 4) = r;
}

// ---------------- heads: one warp per comment row ----------------
__global__ void heads_kernel(const float* __restrict__ h,
                             const float* __restrict__ Wt, const float* __restrict__ bt,
                             const float* __restrict__ Wi, const float* __restrict__ bi,
                             const float* __restrict__ Wm, const float* __restrict__ bm,
                             float* __restrict__ out)
{
    int g = blockIdx.x * blockDim.x + threadIdx.x;
    int row = g >> 5;
    if (row >= NCCOM) return;
    int lane = g & 31;
    float4 hv = *(const float4*)(h + (size_t)row * HD + lane * 4);
    float hval[4] = {hv.x, hv.y, hv.z, hv.w};
    float acc[12];
#pragma unroll
    for (int j = 0; j < 12; j++) acc[j] = 0.f;
#pragma unroll
    for (int r = 0; r < 4; r++) {
        int k = lane * 4 + r;
        float hx = hval[r];
#pragma unroll
        for (int j = 0; j < 5; j++) acc[j] += hx * __ldg(Wt + k * 5 + j);
#pragma unroll
        for (int j = 0; j < 4; j++) acc[5 + j] += hx * __ldg(Wi + k * 4 + j);
#pragma unroll
        for (int j = 0; j < 3; j++) acc[9 + j] += hx * __ldg(Wm + k * 3 + j);
    }
#pragma unroll
    for (int o = 16; o > 0; o >>= 1)
#pragma unroll
        for (int j = 0; j < 12; j++) acc[j] += __shfl_xor_sync(0xffffffffu, acc[j], o);

    if (lane == 0) {
        float tl[5], tp[5], il[4], ip[4];
#pragma unroll
        for (int j = 0; j < 5; j++) { tl[j] = acc[j] + bt[j]; tp[j] = 1.f / (1.f + expf(-tl[j])); }
        float mx = -1e30f;
#pragma unroll
        for (int j = 0; j < 4; j++) { il[j] = acc[5 + j] + bi[j]; mx = fmaxf(mx, il[j]); }
        float se = 0.f;
#pragma unroll
        for (int j = 0; j < 4; j++) { ip[j] = expf(il[j] - mx); se += ip[j]; }
        float inv = 1.f / se;
#pragma unroll
        for (int j = 0; j < 4; j++) ip[j] *= inv;
        float* outT = out;
        float* outI = out + (size_t)NCCOM * 5;
        float* outM = out + (size_t)NCCOM * 9;
#pragma unroll
        for (int j = 0; j < 5; j++) outT[(size_t)row * 5 + j] = tl[j];
#pragma unroll
        for (int j = 0; j < 4; j++) outI[(size_t)row * 4 + j] = il[j];
#pragma unroll
        for (int j = 0; j < 3; j++) {
            float v = acc[9 + j] + bm[j];
#pragma unroll
            for (int t = 0; t < 5; t++) v += tp[t] * __ldg(Wm + (128 + t) * 3 + j);
#pragma unroll
            for (int t = 0; t < 4; t++) v += ip[t] * __ldg(Wm + (133 + t) * 3 + j);
            outM[(size_t)row * 3 + j] = v;
        }
    }
}

// ---------------- host launcher ----------------
extern "C" void kernel_launch(void* const* d_in, const int* in_sizes, int n_in,
                              void* d_out, int out_size)
{
    const float* x_c  = (const float*)d_in[0];
    const float* x_t  = (const float*)d_in[1];
    const float* x_cl = (const float*)d_in[2];
    const float* c1sWl = (const float*)d_in[3];
    const float* c1sbl = (const float*)d_in[4];
    const float* c1sWr = (const float*)d_in[5];
    const float* c1aWl = (const float*)d_in[6];
    const float* c1abl = (const float*)d_in[7];
    const float* c1aWr = (const float*)d_in[8];
    const float* c1tWl = (const float*)d_in[9];
    const float* c1tbl = (const float*)d_in[10];
    const float* c1tWr = (const float*)d_in[11];
    const float* c2sWl = (const float*)d_in[12];
    const float* c2sbl = (const float*)d_in[13];
    const float* c2sWr = (const float*)d_in[14];
    const float* c2aWl = (const float*)d_in[15];
    const float* c2abl = (const float*)d_in[16];
    const float* c2aWr = (const float*)d_in[17];
    const float* c2tWl = (const float*)d_in[18];
    const float* c2tbl = (const float*)d_in[19];
    const float* c2tWr = (const float*)d_in[20];
    const float* Wt = (const float*)d_in[21];
    const float* bt = (const float*)d_in[22];
    const float* Wi = (const float*)d_in[23];
    const float* bi = (const float*)d_in[24];
    const float* Wm = (const float*)d_in[25];
    const float* bm = (const float*)d_in[26];
    const int* ei_sim = (const int*)d_in[27];
    const int* ei_ab  = (const int*)d_in[28];
    const int* ei_tg  = (const int*)d_in[29];

    float *y1, *h1, *agg, *yt, *yc, *cnt;
    int *src, *dst;
    cudaGetSymbolAddress((void**)&y1, g_y1);
    cudaGetSymbolAddress((void**)&h1, g_h1);
    cudaGetSymbolAddress((void**)&agg, g_agg);
    cudaGetSymbolAddress((void**)&yt, g_yt);
    cudaGetSymbolAddress((void**)&yc, g_yc);
    cudaGetSymbolAddress((void**)&cnt, g_cnt);
    cudaGetSymbolAddress((void**)&src, g_src);
    cudaGetSymbolAddress((void**)&dst, g_dst);
    float *W1, *W2, *Wtc, *Wcc, *b1, *b2;
    cudaGetSymbolAddress((void**)&W1, g_W1);
    cudaGetSymbolAddress((void**)&W2, g_W2);
    cudaGetSymbolAddress((void**)&Wtc, g_Wtc);
    cudaGetSymbolAddress((void**)&Wcc, g_Wcc);
    cudaGetSymbolAddress((void**)&b1, g_b1);
    cudaGetSymbolAddress((void**)&b2, g_b2);

    float* agg0 = agg;
    float* agg1 = agg + (size_t)NCCOM * HD;
    float* agg2 = agg + 2 * (size_t)NCCOM * HD;
    float* cnt0 = cnt;
    float* cnt1 = cnt + NCCOM;
    float* cnt2 = cnt + 2 * NCCOM;
    int* srcS = src;            int* dstS = dst;
    int* srcA = src + ESIM;     int* dstA = dst + ESIM;
    int* srcT = src + ESIM + EAB; int* dstT = dst + ESIM + EAB;

    // 1. edge dtype detect + normalize
    detect_kernel<<<1, 1>>>(ei_sim);
    convert_edges<<<(ESIM + 255) / 256, 256>>>(ei_sim, srcS, dstS, ESIM);
    convert_edges<<<(EAB + 255) / 256, 256>>>(ei_ab, srcA, dstA, EAB);
    convert_edges<<<(ETG + 255) / 256, 256>>>(ei_tg, srcT, dstT, ETG);

    // 2. combined weights / biases
    build_weights<<<(164096 + 255) / 256, 256>>>(
        c1sWl, c1sWr, c1aWr, c1tWr, c2sWl, c2sWr, c2aWr, c2tWr,
        c1aWl, c2aWl, c1tWl, c2tWl, c1sbl, c1abl, c1tbl, c2sbl, c2abl, c2tbl);

    // 3. zero counts + aggs, compute in-degrees (reused by both layers)
    zero_kernel<<<2048, 256>>>(cnt, (size_t)3 * NCCOM / 4);
    zero_kernel<<<4096, 256>>>(agg, (size_t)3 * NCCOM * HD / 4);
    count_kernel<<<(ESIM + 255) / 256, 256>>>(dstS, cnt0, ESIM);
    count_kernel<<<(EAB + 255) / 256, 256>>>(dstA, cnt1, EAB);
    count_kernel<<<(ETG + 255) / 256, 256>>>(dstT, cnt2, ETG);

    // 4. layer-1 GEMMs (fused Wl|Wr panels)
    gemm_f32<128, 128, 16, 8, 8><<<dim3((NCCOM + 127) / 128, 2), 256>>>(x_c, W1, y1, NCCOM, 256, 256);
    gemm_f32<128, 128, 16, 8, 8><<<dim3((NTOP + 127) / 128, 2), 256>>>(x_t, Wtc, yt, NTOP, 256, 128);
    gemm_f32<128, 128, 16, 8, 8><<<dim3((NCLM + 127) / 128, 2), 256>>>(x_cl, Wcc, yc, NCLM, 256, 128);

    // 5. layer-1 aggregation + combine
    scatter_kernel<<<(ESIM * 32 + 255) / 256, 256>>>(y1, 256, srcS, dstS, agg0, ESIM);
    scatter_kernel<<<(EAB * 32 + 255) / 256, 256>>>(yt, 256, srcA, dstA, agg1, EAB);
    scatter_kernel<<<(ETG * 32 + 255) / 256, 256>>>(yc, 256, srcT, dstT, agg2, ETG);
    combine_kernel<<<(NCCOM * 32 + 255) / 256, 256>>>(agg0, agg1, agg2, cnt0, cnt1, cnt2,
                                                      y1 + 128, b1, h1);

    // 6. layer 2
    zero_kernel<<<4096, 256>>>(agg, (size_t)3 * NCCOM * HD / 4);
    gemm_f32<128, 128, 16, 8, 8><<<dim3((NCCOM + 127) / 128, 2), 256>>>(h1, W2, y1, NCCOM, 256, 128);
    scatter_kernel<<<(ESIM * 32 + 255) / 256, 256>>>(y1, 256, srcS, dstS, agg0, ESIM);
    scatter_kernel<<<(EAB * 32 + 255) / 256, 256>>>(yt + 128, 256, srcA, dstA, agg1, EAB);
    scatter_kernel<<<(ETG * 32 + 255) / 256, 256>>>(yc + 128, 256, srcT, dstT, agg2, ETG);
    combine_kernel<<<(NCCOM * 32 + 255) / 256, 256>>>(agg0, agg1, agg2, cnt0, cnt1, cnt2,
                                                      y1 + 128, b2, h1);

    // 7. heads
    heads_kernel<<<(NCCOM * 32 + 255) / 256, 256>>>(h1, Wt, bt, Wi, bi, Wm, bm, (float*)d_out);
}

// round 2
// speedup vs baseline: 1.5700x; 1.5700x over previous
#include <cuda_runtime.h>
#include <cstdint>
#include <cmath>

#define NCCOM 100000
#define NTOP  5000
#define NCLM  20000
#define HD 128
#define ESIM 600000
#define EAB  300000
#define ETG  300000
#define ETOT (ESIM+EAB+ETG)
#define NROWS3 (3*NCCOM)
#define SCAN_B 512
#define SCAN_NB ((NROWS3 + SCAN_B - 1) / SCAN_B)

// ---------------- device scratch ----------------
static __device__ float g_y1[(size_t)NCCOM * 256];      // comment GEMM out: [Wl | Wr_sum]
static __device__ float g_h1[(size_t)NCCOM * HD];       // h1
static __device__ float g_yt[(size_t)NTOP * 256];       // topic @ [c1a_Wl | c2a_Wl]
static __device__ float g_yc[(size_t)NCLM * 256];       // claim @ [c1t_Wl | c2t_Wl]
static __device__ int   g_src[ETOT];
static __device__ int   g_dst[ETOT];
static __device__ int   g_deg[NROWS3];
static __device__ int   g_rowptr[NROWS3 + 1];
static __device__ int   g_cursor[NROWS3];
static __device__ int   g_csr[ETOT];
static __device__ int   g_bsum[SCAN_NB];
static __device__ int   g_boff[SCAN_NB];
static __device__ float g_W1[256 * 256];                // [c1s_Wl | sum Wr]
static __device__ float g_W2[128 * 256];
static __device__ float g_Wtc[128 * 256];
static __device__ float g_Wcc[128 * 256];
static __device__ float g_Wh[12 * 128];                 // transposed head weights [j][k]
static __device__ float g_b1[128];
static __device__ float g_b2[128];
static __device__ int   g_is64;

// ---------------- packed f32x2 helpers ----------------
__device__ __forceinline__ void ffma2(unsigned long long& d, unsigned long long a,
                                      unsigned long long b) {
    asm("fma.rn.f32x2 %0, %1, %2, %0;" : "+l"(d) : "l"(a), "l"(b));
}
__device__ __forceinline__ unsigned long long rep2(float x) {
    unsigned long long r;
    asm("mov.b64 %0, {%1, %1};" : "=l"(r) : "f"(x));
    return r;
}
__device__ __forceinline__ void unpack2(unsigned long long v, float& lo, float& hi) {
    asm("mov.b64 {%0, %1}, %2;" : "=f"(lo), "=f"(hi) : "l"(v));
}

// ---------------- edge dtype detection + convert + degree histogram ----------------
__global__ void detect_kernel(const int* __restrict__ raw) {
    int allz = 1;
    for (int i = 0; i < 32; i++)
        if (raw[2 * i + 1] != 0) { allz = 0; break; }
    g_is64 = allz;
}

__global__ void convert_count(const int* __restrict__ raw, int* __restrict__ src,
                              int* __restrict__ dst, int* __restrict__ deg,
                              int E, int degbase) {
    int e = blockIdx.x * blockDim.x + threadIdx.x;
    if (e >= E) return;
    int s, d;
    if (g_is64) {
        s = raw[2 * (size_t)e];
        d = raw[2 * ((size_t)E + e)];
    } else {
        s = raw[e];
        d = raw[(size_t)E + e];
    }
    src[e] = s;
    dst[e] = d;
    atomicAdd(&deg[degbase + d], 1);
}

// ---------------- zero ----------------
__global__ void zero_kernel(float* __restrict__ p, size_t n4) {
    size_t stride = (size_t)gridDim.x * blockDim.x;
    for (size_t i = blockIdx.x * (size_t)blockDim.x + threadIdx.x; i < n4; i += stride)
        ((float4*)p)[i] = make_float4(0.f, 0.f, 0.f, 0.f);
}

// ---------------- scan: block sums -> serial offsets -> write rowptr/cursor ----------------
__global__ void scan_bsum(const int* __restrict__ deg, int* __restrict__ bsum, int n) {
    __shared__ int sm[SCAN_B];
    int i = blockIdx.x * SCAN_B + threadIdx.x;
    sm[threadIdx.x] = (i < n) ? deg[i] : 0;
    __syncthreads();
    for (int o = SCAN_B / 2; o > 0; o >>= 1) {
        if (threadIdx.x < o) sm[threadIdx.x] += sm[threadIdx.x + o];
        __syncthreads();
    }
    if (threadIdx.x == 0) bsum[blockIdx.x] = sm[0];
}

__global__ void scan_offsets(const int* __restrict__ bsum, int* __restrict__ boff, int nb) {
    int acc = 0;
    for (int b = 0; b < nb; b++) { boff[b] = acc; acc += bsum[b]; }
}

__global__ void scan_write(const int* __restrict__ deg, const int* __restrict__ boff,
                           int* __restrict__ rowptr, int* __restrict__ cursor, int n) {
    __shared__ int sm[SCAN_B];
    int i = blockIdx.x * SCAN_B + threadIdx.x;
    int v = (i < n) ? deg[i] : 0;
    sm[threadIdx.x] = v;
    __syncthreads();
    for (int o = 1; o < SCAN_B; o <<= 1) {
        int t = (threadIdx.x >= o) ? sm[threadIdx.x - o] : 0;
        __syncthreads();
        sm[threadIdx.x] += t;
        __syncthreads();
    }
    if (i < n) {
        int ex = boff[blockIdx.x] + sm[threadIdx.x] - v;
        rowptr[i] = ex;
        cursor[i] = ex;
        if (i == n - 1) rowptr[n] = boff[blockIdx.x] + sm[threadIdx.x];
    }
}

__global__ void fill_csr(const int* __restrict__ src, const int* __restrict__ dst,
                         int* __restrict__ cursor, int* __restrict__ csr, int E, int degbase) {
    int e = blockIdx.x * blockDim.x + threadIdx.x;
    if (e >= E) return;
    int pos = atomicAdd(&cursor[degbase + dst[e]], 1);
    csr[pos] = src[e];
}

// ---------------- combined weight construction ----------------
__global__ void build_weights(
    const float* __restrict__ c1sWl, const float* __restrict__ c1sWr,
    const float* __restrict__ c1aWr, const float* __restrict__ c1tWr,
    const float* __restrict__ c2sWl, const float* __restrict__ c2sWr,
    const float* __restrict__ c2aWr, const float* __restrict__ c2tWr,
    const float* __restrict__ c1aWl, const float* __restrict__ c2aWl,
    const float* __restrict__ c1tWl, const float* __restrict__ c2tWl,
    const float* __restrict__ b1s, const float* __restrict__ b1a, const float* __restrict__ b1t,
    const float* __restrict__ b2s, const float* __restrict__ b2a, const float* __restrict__ b2t,
    const float* __restrict__ Wt, const float* __restrict__ Wi, const float* __restrict__ Wm)
{
    int i = blockIdx.x * blockDim.x + threadIdx.x;
    if (i < 65536) {                      // W1: [256, 256]
        int k = i >> 8, j = i & 255;
        g_W1[i] = (j < 128) ? c1sWl[k * 128 + j]
                            : (c1sWr[k * 128 + j - 128] + c1aWr[k * 128 + j - 128] + c1tWr[k * 128 + j - 128]);
    } else if (i < 98304) {               // W2: [128, 256]
        int t = i - 65536; int k = t >> 8, j = t & 255;
        g_W2[t] = (j < 128) ? c2sWl[k * 128 + j]
                            : (c2sWr[k * 128 + j - 128] + c2aWr[k * 128 + j - 128] + c2tWr[k * 128 + j - 128]);
    } else if (i < 131072) {              // Wtc: [128, 256]
        int t = i - 98304; int k = t >> 8, j = t & 255;
        g_Wtc[t] = (j < 128) ? c1aWl[k * 128 + j] : c2aWl[k * 128 + j - 128];
    } else if (i < 163840) {              // Wcc: [128, 256]
        int t = i - 131072; int k = t >> 8, j = t & 255;
        g_Wcc[t] = (j < 128) ? c1tWl[k * 128 + j] : c2tWl[k * 128 + j - 128];
    } else if (i < 164096) {
        int t = i - 163840;
        if (t < 128) g_b1[t] = b1s[t] + b1a[t] + b1t[t];
        else { int u = t - 128; g_b2[u] = b2s[u] + b2a[u] + b2t[u]; }
    } else if (i < 164096 + 1536) {       // transposed heads weights
        int t = i - 164096;               // t = j*128 + k
        int j = t >> 7, k = t & 127;
        float v;
        if (j < 5) v = Wt[k * 5 + j];
        else if (j < 9) v = Wi[k * 4 + (j - 5)];
        else v = Wm[k * 3 + (j - 9)];
        g_Wh[t] = v;
    }
}

// ---------------- FFMA2 GEMM: C[M,N] = A[M,K] @ B[K,N], BM=BN=128, TM=TN=8 ----------------
template <int BK>
__global__ void __launch_bounds__(256, 2)
gemm_x2(const float* __restrict__ A, const float* __restrict__ B, float* __restrict__ C,
        int M, int N, int K)
{
    constexpr int BM = 128, BN = 128;
    __shared__ float As[BK][BM + 4];
    __shared__ float Bs[BK][BN];
    const int tid = threadIdx.x;
    const int tx = tid & 15;
    const int ty = tid >> 4;
    const int bm0 = blockIdx.x * BM;
    const int bn0 = blockIdx.y * BN;

    unsigned long long acc[4][8];
#pragma unroll
    for (int i = 0; i < 4; i++)
#pragma unroll
        for (int j = 0; j < 8; j++) acc[i][j] = 0ull;

    for (int k0 = 0; k0 < K; k0 += BK) {
#pragma unroll
        for (int f = tid; f < BM * BK / 4; f += 256) {
            int row = f / (BK / 4);
            int k4 = f % (BK / 4);
            float4 v = make_float4(0.f, 0.f, 0.f, 0.f);
            if (bm0 + row < M)
                v = *(const float4*)(A + (size_t)(bm0 + row) * K + k0 + k4 * 4);
            As[k4 * 4 + 0][row] = v.x;
            As[k4 * 4 + 1][row] = v.y;
            As[k4 * 4 + 2][row] = v.z;
            As[k4 * 4 + 3][row] = v.w;
        }
#pragma unroll
        for (int f = tid; f < BK * BN / 4; f += 256) {
            int kr = f / (BN / 4);
            int c4 = f % (BN / 4);
            *(float4*)&Bs[kr][c4 * 4] = *(const float4*)(B + (size_t)(k0 + kr) * N + bn0 + c4 * 4);
        }
        __syncthreads();
#pragma unroll
        for (int kk = 0; kk < BK; kk++) {
            const float* ar = &As[kk][ty * 8];
            unsigned long long a0 = *(const unsigned long long*)(ar + 0);
            unsigned long long a1 = *(const unsigned long long*)(ar + 2);
            unsigned long long a2 = *(const unsigned long long*)(ar + 4);
            unsigned long long a3 = *(const unsigned long long*)(ar + 6);
            float4 bl = *(const float4*)&Bs[kk][tx * 8];
            float4 bh = *(const float4*)&Bs[kk][tx * 8 + 4];
            unsigned long long rb[8];
            rb[0] = rep2(bl.x); rb[1] = rep2(bl.y); rb[2] = rep2(bl.z); rb[3] = rep2(bl.w);
            rb[4] = rep2(bh.x); rb[5] = rep2(bh.y); rb[6] = rep2(bh.z); rb[7] = rep2(bh.w);
#pragma unroll
            for (int j = 0; j < 8; j++) {
                ffma2(acc[0][j], a0, rb[j]);
                ffma2(acc[1][j], a1, rb[j]);
                ffma2(acc[2][j], a2, rb[j]);
                ffma2(acc[3][j], a3, rb[j]);
            }
        }
        __syncthreads();
    }
#pragma unroll
    for (int i2 = 0; i2 < 4; i2++) {
        float lo[8], hi[8];
#pragma unroll
        for (int j = 0; j < 8; j++) unpack2(acc[i2][j], lo[j], hi[j]);
        int r0 = bm0 + ty * 8 + 2 * i2;
        if (r0 < M) {
            float* cp = C + (size_t)r0 * N + bn0 + tx * 8;
            *(float4*)cp = make_float4(lo[0], lo[1], lo[2], lo[3]);
            *(float4*)(cp + 4) = make_float4(lo[4], lo[5], lo[6], lo[7]);
        }
        if (r0 + 1 < M) {
            float* cp = C + (size_t)(r0 + 1) * N + bn0 + tx * 8;
            *(float4*)cp = make_float4(hi[0], hi[1], hi[2], hi[3]);
            *(float4*)(cp + 4) = make_float4(hi[4], hi[5], hi[6], hi[7]);
        }
    }
}

// ---------------- gather-aggregate (+ fused combine, + optional fused heads) ----------------
template <bool HEADS>
__global__ void gather_kernel(
    const float* __restrict__ yS, const float* __restrict__ yA, const float* __restrict__ yT,
    const int* __restrict__ rowptr, const int* __restrict__ csr,
    const float* __restrict__ selfp, const float* __restrict__ bias,
    float* __restrict__ out,
    const float* __restrict__ Wh, const float* __restrict__ Wm,
    const float* __restrict__ bt, const float* __restrict__ bi, const float* __restrict__ bm)
{
    int g = blockIdx.x * blockDim.x + threadIdx.x;
    int r = g >> 5;
    if (r >= NCCOM) return;
    int lane = g & 31;
    int c4 = lane * 4;

    float4 acc = make_float4(0.f, 0.f, 0.f, 0.f);
    const float* ys[3] = {yS, yA, yT};
#pragma unroll
    for (int t = 0; t < 3; t++) {
        int s0 = __ldg(rowptr + t * NCCOM + r);
        int s1 = __ldg(rowptr + t * NCCOM + r + 1);
        float4 loc = make_float4(0.f, 0.f, 0.f, 0.f);
        for (int e = s0; e < s1; e++) {
            int s = __ldg(csr + e);
            float4 v = *(const float4*)(ys[t] + (size_t)s * 256 + c4);
            loc.x += v.x; loc.y += v.y; loc.z += v.z; loc.w += v.w;
        }
        float inv = 1.f / fmaxf((float)(s1 - s0), 1.f);
        acc.x += loc.x * inv; acc.y += loc.y * inv;
        acc.z += loc.z * inv; acc.w += loc.w * inv;
    }
    float4 sv = *(const float4*)(selfp + (size_t)r * 256 + c4);
    float4 bv = *(const float4*)(bias + c4);
    float h0 = fmaxf(acc.x + sv.x + bv.x, 0.f);
    float h1 = fmaxf(acc.y + sv.y + bv.y, 0.f);
    float h2 = fmaxf(acc.z + sv.z + bv.z, 0.f);
    float h3 = fmaxf(acc.w + sv.w + bv.w, 0.f);

    if (!HEADS) {
        *(float4*)(out + (size_t)r * HD + c4) = make_float4(h0, h1, h2, h3);
        return;
    }

    // fused heads
    float a12[12];
#pragma unroll
    for (int j = 0; j < 12; j++) {
        float4 w = *(const float4*)(Wh + j * 128 + c4);
        a12[j] = h0 * w.x + h1 * w.y + h2 * w.z + h3 * w.w;
    }
#pragma unroll
    for (int o = 16; o > 0; o >>= 1)
#pragma unroll
        for (int j = 0; j < 12; j++) a12[j] += __shfl_xor_sync(0xffffffffu, a12[j], o);

    if (lane == 0) {
        float tl[5], tp[5], il[4], ip[4];
#pragma unroll
        for (int j = 0; j < 5; j++) { tl[j] = a12[j] + bt[j]; tp[j] = 1.f / (1.f + expf(-tl[j])); }
        float mx = -1e30f;
#pragma unroll
        for (int j = 0; j < 4; j++) { il[j] = a12[5 + j] + bi[j]; mx = fmaxf(mx, il[j]); }
        float se = 0.f;
#pragma unroll
        for (int j = 0; j < 4; j++) { ip[j] = expf(il[j] - mx); se += ip[j]; }
        float inv = 1.f / se;
#pragma unroll
        for (int j = 0; j < 4; j++) ip[j] *= inv;
        float* outT = out;
        float* outI = out + (size_t)NCCOM * 5;
        float* outM = out + (size_t)NCCOM * 9;
#pragma unroll
        for (int j = 0; j < 5; j++) outT[(size_t)r * 5 + j] = tl[j];
#pragma unroll
        for (int j = 0; j < 4; j++) outI[(size_t)r * 4 + j] = il[j];
#pragma unroll
        for (int j = 0; j < 3; j++) {
            float v = a12[9 + j] + bm[j];
#pragma unroll
            for (int t = 0; t < 5; t++) v += tp[t] * __ldg(Wm + (128 + t) * 3 + j);
#pragma unroll
            for (int t = 0; t < 4; t++) v += ip[t] * __ldg(Wm + (133 + t) * 3 + j);
            outM[(size_t)r * 3 + j] = v;
        }
    }
}

// ---------------- host launcher ----------------
extern "C" void kernel_launch(void* const* d_in, const int* in_sizes, int n_in,
                              void* d_out, int out_size)
{
    const float* x_c  = (const float*)d_in[0];
    const float* x_t  = (const float*)d_in[1];
    const float* x_cl = (const float*)d_in[2];
    const float* c1sWl = (const float*)d_in[3];
    const float* c1sbl = (const float*)d_in[4];
    const float* c1sWr = (const float*)d_in[5];
    const float* c1aWl = (const float*)d_in[6];
    const float* c1abl = (const float*)d_in[7];
    const float* c1aWr = (const float*)d_in[8];
    const float* c1tWl = (const float*)d_in[9];
    const float* c1tbl = (const float*)d_in[10];
    const float* c1tWr = (const float*)d_in[11];
    const float* c2sWl = (const float*)d_in[12];
    const float* c2sbl = (const float*)d_in[13];
    const float* c2sWr = (const float*)d_in[14];
    const float* c2aWl = (const float*)d_in[15];
    const float* c2abl = (const float*)d_in[16];
    const float* c2aWr = (const float*)d_in[17];
    const float* c2tWl = (const float*)d_in[18];
    const float* c2tbl = (const float*)d_in[19];
    const float* c2tWr = (const float*)d_in[20];
    const float* Wt = (const float*)d_in[21];
    const float* bt = (const float*)d_in[22];
    const float* Wi = (const float*)d_in[23];
    const float* bi = (const float*)d_in[24];
    const float* Wm = (const float*)d_in[25];
    const float* bm = (const float*)d_in[26];
    const int* ei_sim = (const int*)d_in[27];
    const int* ei_ab  = (const int*)d_in[28];
    const int* ei_tg  = (const int*)d_in[29];

    float *y1, *h1, *yt, *yc;
    int *src, *dst, *deg, *rowptr, *cursor, *csr, *bsum, *boff;
    float *W1, *W2, *Wtc, *Wcc, *Wh, *b1, *b2;
    cudaGetSymbolAddress((void**)&y1, g_y1);
    cudaGetSymbolAddress((void**)&h1, g_h1);
    cudaGetSymbolAddress((void**)&yt, g_yt);
    cudaGetSymbolAddress((void**)&yc, g_yc);
    cudaGetSymbolAddress((void**)&src, g_src);
    cudaGetSymbolAddress((void**)&dst, g_dst);
    cudaGetSymbolAddress((void**)&deg, g_deg);
    cudaGetSymbolAddress((void**)&rowptr, g_rowptr);
    cudaGetSymbolAddress((void**)&cursor, g_cursor);
    cudaGetSymbolAddress((void**)&csr, g_csr);
    cudaGetSymbolAddress((void**)&bsum, g_bsum);
    cudaGetSymbolAddress((void**)&boff, g_boff);
    cudaGetSymbolAddress((void**)&W1, g_W1);
    cudaGetSymbolAddress((void**)&W2, g_W2);
    cudaGetSymbolAddress((void**)&Wtc, g_Wtc);
    cudaGetSymbolAddress((void**)&Wcc, g_Wcc);
    cudaGetSymbolAddress((void**)&Wh, g_Wh);
    cudaGetSymbolAddress((void**)&b1, g_b1);
    cudaGetSymbolAddress((void**)&b2, g_b2);

    int* srcS = src;              int* dstS = dst;
    int* srcA = src + ESIM;       int* dstA = dst + ESIM;
    int* srcT = src + ESIM + EAB; int* dstT = dst + ESIM + EAB;

    // 1. edge prep: detect dtype, convert + degree histogram
    detect_kernel<<<1, 1>>>(ei_sim);
    zero_kernel<<<512, 256>>>((float*)deg, NROWS3 / 4);
    convert_count<<<(ESIM + 255) / 256, 256>>>(ei_sim, srcS, dstS, deg, ESIM, 0);
    convert_count<<<(EAB + 255) / 256, 256>>>(ei_ab, srcA, dstA, deg, EAB, NCCOM);
    convert_count<<<(ETG + 255) / 256, 256>>>(ei_tg, srcT, dstT, deg, ETG, 2 * NCCOM);

    // 2. CSR build: scan + fill
    scan_bsum<<<SCAN_NB, SCAN_B>>>(deg, bsum, NROWS3);
    scan_offsets<<<1, 1>>>(bsum, boff, SCAN_NB);
    scan_write<<<SCAN_NB, SCAN_B>>>(deg, boff, rowptr, cursor, NROWS3);
    fill_csr<<<(ESIM + 255) / 256, 256>>>(srcS, dstS, cursor, csr, ESIM, 0);
    fill_csr<<<(EAB + 255) / 256, 256>>>(srcA, dstA, cursor, csr, EAB, NCCOM);
    fill_csr<<<(ETG + 255) / 256, 256>>>(srcT, dstT, cursor, csr, ETG, 2 * NCCOM);

    // 3. combined weights
    build_weights<<<(164096 + 1536 + 255) / 256, 256>>>(
        c1sWl, c1sWr, c1aWr, c1tWr, c2sWl, c2sWr, c2aWr, c2tWr,
        c1aWl, c2aWl, c1tWl, c2tWl, c1sbl, c1abl, c1tbl, c2sbl, c2abl, c2tbl,
        Wt, Wi, Wm);

    // 4. layer-1 GEMMs
    gemm_x2<16><<<dim3((NCCOM + 127) / 128, 2), 256>>>(x_c, W1, y1, NCCOM, 256, 256);
    gemm_x2<16><<<dim3((NTOP + 127) / 128, 2), 256>>>(x_t, Wtc, yt, NTOP, 256, 128);
    gemm_x2<16><<<dim3((NCLM + 127) / 128, 2), 256>>>(x_cl, Wcc, yc, NCLM, 256, 128);

    // 5. layer-1 gather + combine
    gather_kernel<false><<<(NCCOM * 32 + 255) / 256, 256>>>(
        y1, yt, yc, rowptr, csr, y1 + 128, b1, h1,
        nullptr, nullptr, nullptr, nullptr, nullptr);

    // 6. layer-2 GEMM + gather + fused heads
    gemm_x2<16><<<dim3((NCCOM + 127) / 128, 2), 256>>>(h1, W2, y1, NCCOM, 256, 128);
    gather_kernel<true><<<(NCCOM * 32 + 255) / 256, 256>>>(
        y1, yt + 128, yc + 128, rowptr, csr, y1 + 128, b2, (float*)d_out,
        Wh, Wm, bt, bi, bm);
}